// round 8
// baseline (speedup 1.0000x reference)
#include <cuda_runtime.h>
#include <cuda_bf16.h>
#include <cstdint>

#define N_USER 50000
#define N_ITEM 50000
#define N_NODES 100000
#define NNZ 3200000
#define EMB 64
#define N_LAYERS 3
#define BATCH 4096
#define OUT_EMB 256           // EMB * (N_LAYERS + 1)
#define ELL_CAP 96            // Poisson(32): P(deg>=96) ~ 3e-19 per row
#define KT 16                 // K-tile for dense
#define DROWS 128             // rows per dense block

// Scratch (no cudaMalloc allowed): __device__ globals.
__device__ float g_ego[N_NODES * EMB];        // current (unnormalized) embeddings
__device__ float g_side[N_NODES * EMB];       // SpMM result
__device__ float g_all[N_NODES * OUT_EMB];    // [ego0 | n1 | n2 | n3]
__device__ int   g_cnt[N_NODES];              // per-row degree (built once)
__device__ int2  g_ell[(size_t)N_NODES * ELL_CAP]; // padded rows of {col, val_bits}

// ---------------------------------------------------------------------------
// packed f32x2 helpers (sm_103a FFMA2 — only reachable via PTX)
// ---------------------------------------------------------------------------
__device__ __forceinline__ unsigned long long ffma2(unsigned long long a,
                                                    unsigned long long b,
                                                    unsigned long long c) {
    unsigned long long d;
    asm("fma.rn.f32x2 %0, %1, %2, %3;" : "=l"(d) : "l"(a), "l"(b), "l"(c));
    return d;
}
__device__ __forceinline__ unsigned long long pack2(float x) {
    unsigned long long d;
    asm("mov.b64 %0, {%1, %1};" : "=l"(d) : "f"(x));
    return d;
}
__device__ __forceinline__ float2 unpack2(unsigned long long d) {
    float2 f;
    asm("mov.b64 {%0, %1}, %2;" : "=f"(f.x), "=f"(f.y) : "l"(d));
    return f;
}

// ---------------------------------------------------------------------------
// Init: ego = concat(user_emb, item_emb); all[:, 0:64] = ego; zero degrees.
// ---------------------------------------------------------------------------
__global__ __launch_bounds__(256) void k_init(const float* __restrict__ ue,
                                              const float* __restrict__ ie) {
    int idx = blockIdx.x * blockDim.x + threadIdx.x;   // float4 index
    const int total = N_NODES * EMB / 4;
    if (idx >= total) return;
    if (idx < N_NODES) g_cnt[idx] = 0;
    int r = idx >> 4;          // row (EMB/4 = 16 float4 per row)
    int c = idx & 15;
    float4 v = (r < N_USER)
        ? reinterpret_cast<const float4*>(ue)[(size_t)r * 16 + c]
        : reinterpret_cast<const float4*>(ie)[(size_t)(r - N_USER) * 16 + c];
    reinterpret_cast<float4*>(g_ego)[idx] = v;
    *reinterpret_cast<float4*>(&g_all[(size_t)r * OUT_EMB + c * 4]) = v;
}

// ---------------------------------------------------------------------------
// ELL build: single pass, no scan. pos = atomicAdd(cnt[row]); write slot.
// ---------------------------------------------------------------------------
__global__ __launch_bounds__(256) void k_build(const int* __restrict__ arow,
                                               const int* __restrict__ acol,
                                               const float* __restrict__ aval) {
    int e = blockIdx.x * blockDim.x + threadIdx.x;
    if (e >= NNZ) return;
    int r = arow[e];
    int pos = atomicAdd(&g_cnt[r], 1);
    if (pos < ELL_CAP)
        g_ell[(size_t)r * ELL_CAP + pos] = make_int2(acol[e], __float_as_int(aval[e]));
}

// ---------------------------------------------------------------------------
// ELL SpMM: one warp per row; lane l accumulates dims [2l, 2l+1] in registers.
// ---------------------------------------------------------------------------
__global__ __launch_bounds__(256) void k_spmm_ell() {
    __shared__ int2 se[8][32];
    int gw = (blockIdx.x * 256 + threadIdx.x) >> 5;   // uniform within warp
    if (gw >= N_NODES) return;
    int lane = threadIdx.x & 31;
    int wl = threadIdx.x >> 5;
    int cnt = g_cnt[gw];
    if (cnt > ELL_CAP) cnt = ELL_CAP;
    const int2* row = &g_ell[(size_t)gw * ELL_CAP];
    float2 acc = make_float2(0.f, 0.f);
    for (int base = 0; base < cnt; base += 32) {
        int idx = base + lane;
        int2 ev = make_int2(0, 0);
        if (idx < cnt) ev = row[idx];
        se[wl][lane] = ev;
        __syncwarp();
        int n = cnt - base; if (n > 32) n = 32;
        #pragma unroll 4
        for (int j = 0; j < n; j++) {
            int2 e2 = se[wl][j];
            float val = __int_as_float(e2.y);
            float2 x = *reinterpret_cast<const float2*>(
                &g_ego[(size_t)e2.x * EMB + lane * 2]);
            acc.x = fmaf(val, x.x, acc.x);
            acc.y = fmaf(val, x.y, acc.y);
        }
        __syncwarp();
    }
    *reinterpret_cast<float2*>(&g_side[(size_t)gw * EMB + lane * 2]) = acc;
}

// ---------------------------------------------------------------------------
// Dense layer: ego_new = leaky( side@Wg + bg + (ego*side)@Wb + bb )
// 256 threads, 128 rows/block. Thread = 4 rows x 8 cols (ffma2-packed acc).
// K tiled by 16; s/p transposed in smem (conflict-free broadcast reads).
// launch_bounds(256,2): regs<=128 -> 2 CTAs/SM (occ 25%, was 12.7%).
// ---------------------------------------------------------------------------
__global__ __launch_bounds__(256, 2) void k_dense(const float* __restrict__ Wg,
                                                  const float* __restrict__ bg,
                                                  const float* __restrict__ Wb,
                                                  const float* __restrict__ bb,
                                                  int layer) {
    __shared__ float sWg[KT * EMB];        // 4KB
    __shared__ float sWb[KT * EMB];        // 4KB
    __shared__ float sS[KT * DROWS];       // 8KB  sS[i][row]
    __shared__ float sP[KT * DROWS];       // 8KB  sP[i][row]

    const int tid  = threadIdx.x;
    const int lane = tid & 31;
    const int wid  = tid >> 5;
    const int jt   = lane & 7;        // col-group 0..7 (8 cols each)
    const int slot = lane >> 3;       // 0..3 (4 rows each)
    const int lrow0 = wid * 16 + slot * 4;     // first of this thread's 4 rows
    const int row_base = blockIdx.x * DROWS;

    const float* Wgk = Wg + (size_t)layer * EMB * EMB;
    const float* Wbk = Wb + (size_t)layer * EMB * EMB;

    // bias seed from global (uniform per-jt addresses -> L1 broadcast)
    unsigned long long acc[4][4];
    {
        const float4* bg4 = reinterpret_cast<const float4*>(bg + layer * EMB);
        const float4* bb4 = reinterpret_cast<const float4*>(bb + layer * EMB);
        float4 b0 = bg4[jt * 2],     b1 = bg4[jt * 2 + 1];
        float4 c0 = bb4[jt * 2],     c1 = bb4[jt * 2 + 1];
        float bsum[8] = {b0.x + c0.x, b0.y + c0.y, b0.z + c0.z, b0.w + c0.w,
                         b1.x + c1.x, b1.y + c1.y, b1.z + c1.z, b1.w + c1.w};
        #pragma unroll
        for (int r = 0; r < 4; r++)
            #pragma unroll
            for (int c = 0; c < 4; c++) {
                unsigned long long d;
                asm("mov.b64 %0, {%1, %2};" : "=l"(d)
                    : "f"(bsum[c * 2]), "f"(bsum[c * 2 + 1]));
                acc[r][c] = d;
            }
    }

    // staging role: row = tid & 127; half (tid>>7) stages 8 of the 16 dims
    const int srow = tid & (DROWS - 1);
    const int crow = min(row_base + srow, N_NODES - 1);
    const int ihalf = (tid >> 7) * 8;     // 0 or 8

    for (int kt = 0; kt < EMB / KT; kt++) {
        // --- stage W tile [KT][64]: one float4 per thread per matrix ---
        {
            int i_l = tid >> 4, c4 = tid & 15;
            size_t g = (size_t)(kt * KT + i_l) * EMB + c4 * 4;
            float4 wgv = *reinterpret_cast<const float4*>(&Wgk[g]);
            float4 wbv = *reinterpret_cast<const float4*>(&Wbk[g]);
            *reinterpret_cast<float4*>(&sWg[i_l * EMB + c4 * 4]) = wgv;
            *reinterpret_cast<float4*>(&sWb[i_l * EMB + c4 * 4]) = wbv;
        }
        // --- stage s/p transposed: 2 float4 per thread ---
        #pragma unroll
        for (int q = 0; q < 2; q++) {
            int i0 = ihalf + q * 4;
            size_t g = (size_t)crow * EMB + kt * KT + i0;
            float4 sv = *reinterpret_cast<const float4*>(&g_side[g]);
            float4 ev = *reinterpret_cast<const float4*>(&g_ego[g]);
            sS[(i0 + 0) * DROWS + srow] = sv.x;
            sS[(i0 + 1) * DROWS + srow] = sv.y;
            sS[(i0 + 2) * DROWS + srow] = sv.z;
            sS[(i0 + 3) * DROWS + srow] = sv.w;
            sP[(i0 + 0) * DROWS + srow] = sv.x * ev.x;
            sP[(i0 + 1) * DROWS + srow] = sv.y * ev.y;
            sP[(i0 + 2) * DROWS + srow] = sv.z * ev.z;
            sP[(i0 + 3) * DROWS + srow] = sv.w * ev.w;
        }
        __syncthreads();

        #pragma unroll
        for (int i = 0; i < KT; i++) {
            ulonglong2 ga = *reinterpret_cast<const ulonglong2*>(&sWg[i * EMB + jt * 8]);
            ulonglong2 gb = *reinterpret_cast<const ulonglong2*>(&sWg[i * EMB + jt * 8 + 4]);
            ulonglong2 ha = *reinterpret_cast<const ulonglong2*>(&sWb[i * EMB + jt * 8]);
            ulonglong2 hb = *reinterpret_cast<const ulonglong2*>(&sWb[i * EMB + jt * 8 + 4]);
            #pragma unroll
            for (int r = 0; r < 4; r++) {
                unsigned long long s2 = pack2(sS[i * DROWS + lrow0 + r]);
                unsigned long long p2 = pack2(sP[i * DROWS + lrow0 + r]);
                acc[r][0] = ffma2(s2, ga.x, acc[r][0]);
                acc[r][0] = ffma2(p2, ha.x, acc[r][0]);
                acc[r][1] = ffma2(s2, ga.y, acc[r][1]);
                acc[r][1] = ffma2(p2, ha.y, acc[r][1]);
                acc[r][2] = ffma2(s2, gb.x, acc[r][2]);
                acc[r][2] = ffma2(p2, hb.x, acc[r][2]);
                acc[r][3] = ffma2(s2, gb.y, acc[r][3]);
                acc[r][3] = ffma2(p2, hb.y, acc[r][3]);
            }
        }
        __syncthreads();
    }

    // --- epilogue: leaky + row-norm (8-lane shfl) + stores ---
    #pragma unroll
    for (int r = 0; r < 4; r++) {
        float2 u0 = unpack2(acc[r][0]), u1 = unpack2(acc[r][1]);
        float2 u2 = unpack2(acc[r][2]), u3 = unpack2(acc[r][3]);
        float a[8] = {u0.x, u0.y, u1.x, u1.y, u2.x, u2.y, u3.x, u3.y};
        float n2 = 0.f;
        #pragma unroll
        for (int c = 0; c < 8; c++) {
            float v = a[c];
            v = (v > 0.f) ? v : 0.2f * v;
            a[c] = v;
            n2 += v * v;
        }
        #pragma unroll
        for (int m = 1; m < 8; m <<= 1)
            n2 += __shfl_xor_sync(0xffffffffu, n2, m, 8);
        float inv = 1.0f / fmaxf(sqrtf(n2), 1e-12f);

        int grow = row_base + lrow0 + r;
        if (grow < N_NODES) {
            float4 lo = make_float4(a[0], a[1], a[2], a[3]);
            float4 hi = make_float4(a[4], a[5], a[6], a[7]);
            float* egp = &g_ego[(size_t)grow * EMB + jt * 8];
            reinterpret_cast<float4*>(egp)[0] = lo;
            reinterpret_cast<float4*>(egp)[1] = hi;
            float* alp = &g_all[(size_t)grow * OUT_EMB + (layer + 1) * EMB + jt * 8];
            reinterpret_cast<float4*>(alp)[0] =
                make_float4(lo.x * inv, lo.y * inv, lo.z * inv, lo.w * inv);
            reinterpret_cast<float4*>(alp)[1] =
                make_float4(hi.x * inv, hi.y * inv, hi.z * inv, hi.w * inv);
        }
    }
}

// ---------------------------------------------------------------------------
// Final gather: out = [ all[users], all[N_USER+pos], all[N_USER+neg] ]
// ---------------------------------------------------------------------------
__global__ __launch_bounds__(256) void k_gather(const int* __restrict__ users,
                                                const int* __restrict__ pos,
                                                const int* __restrict__ neg,
                                                float* __restrict__ out) {
    int t = blockIdx.x * blockDim.x + threadIdx.x;
    const int total = 3 * BATCH * (OUT_EMB / 4);
    if (t >= total) return;
    int g = t / (BATCH * (OUT_EMB / 4));
    int rem = t - g * (BATCH * (OUT_EMB / 4));
    int b = rem >> 6;          // OUT_EMB/4 = 64 float4 per row
    int f = rem & 63;
    int src;
    if (g == 0)      src = users[b];
    else if (g == 1) src = N_USER + pos[b];
    else             src = N_USER + neg[b];
    reinterpret_cast<float4*>(out)[t] =
        reinterpret_cast<const float4*>(&g_all[(size_t)src * OUT_EMB])[f];
}

// ---------------------------------------------------------------------------
extern "C" void kernel_launch(void* const* d_in, const int* in_sizes, int n_in,
                              void* d_out, int out_size) {
    const int*   users = (const int*)   d_in[0];
    const int*   pos   = (const int*)   d_in[1];
    const int*   neg   = (const int*)   d_in[2];
    const int*   arow  = (const int*)   d_in[3];
    const int*   acol  = (const int*)   d_in[4];
    const float* aval  = (const float*) d_in[5];
    const float* ue    = (const float*) d_in[6];
    const float* ie    = (const float*) d_in[7];
    const float* Wg    = (const float*) d_in[8];
    const float* bg    = (const float*) d_in[9];
    const float* Wb    = (const float*) d_in[10];
    const float* bb    = (const float*) d_in[11];
    float* out = (float*)d_out;

    k_init<<<(N_NODES * EMB / 4 + 255) / 256, 256>>>(ue, ie);

    // One-pass ELL build (no histogram, no scan) — amortized over 3 layers
    k_build<<<(NNZ + 255) / 256, 256>>>(arow, acol, aval);

    const int dense_grid = (N_NODES + DROWS - 1) / DROWS;
    for (int k = 0; k < N_LAYERS; k++) {
        k_spmm_ell<<<(N_NODES * 32 + 255) / 256, 256>>>();
        k_dense<<<dense_grid, 256>>>(Wg, bg, Wb, bb, k);
    }

    k_gather<<<(3 * BATCH * (OUT_EMB / 4) + 255) / 256, 256>>>(users, pos, neg, out);
}

// round 9
// speedup vs baseline: 1.1469x; 1.1469x over previous
#include <cuda_runtime.h>
#include <cuda_bf16.h>
#include <cstdint>

#define N_USER 50000
#define N_ITEM 50000
#define N_NODES 100000
#define NNZ 3200000
#define EMB 64
#define N_LAYERS 3
#define BATCH 4096
#define OUT_EMB 256           // EMB * (N_LAYERS + 1)
#define ELL_CAP 96            // Poisson(32): P(deg>=96) ~ 3e-19 per row
#define KT 16                 // K-tile for dense
#define DROWS 256             // rows per dense block

// Scratch (no cudaMalloc allowed): __device__ globals.
__device__ float g_ego[N_NODES * EMB];        // current (unnormalized) embeddings
__device__ float g_side[N_NODES * EMB];       // SpMM result
__device__ float g_all[N_NODES * OUT_EMB];    // [ego0 | n1 | n2 | n3]
__device__ int   g_cnt[N_NODES];              // per-row degree (built once)
__device__ int2  g_ell[(size_t)N_NODES * ELL_CAP]; // padded rows of {col, val_bits}

// ---------------------------------------------------------------------------
// packed f32x2 helpers (sm_103a FFMA2 — only reachable via PTX)
// ---------------------------------------------------------------------------
__device__ __forceinline__ unsigned long long ffma2(unsigned long long a,
                                                    unsigned long long b,
                                                    unsigned long long c) {
    unsigned long long d;
    asm("fma.rn.f32x2 %0, %1, %2, %3;" : "=l"(d) : "l"(a), "l"(b), "l"(c));
    return d;
}
__device__ __forceinline__ unsigned long long pack2(float x) {
    unsigned long long d;
    asm("mov.b64 %0, {%1, %1};" : "=l"(d) : "f"(x));
    return d;
}
__device__ __forceinline__ float2 unpack2(unsigned long long d) {
    float2 f;
    asm("mov.b64 {%0, %1}, %2;" : "=f"(f.x), "=f"(f.y) : "l"(d));
    return f;
}

// ---------------------------------------------------------------------------
// Init: ego = concat(user_emb, item_emb); all[:, 0:64] = ego; zero degrees.
// ---------------------------------------------------------------------------
__global__ __launch_bounds__(256) void k_init(const float* __restrict__ ue,
                                              const float* __restrict__ ie) {
    int idx = blockIdx.x * blockDim.x + threadIdx.x;   // float4 index
    const int total = N_NODES * EMB / 4;
    if (idx >= total) return;
    if (idx < N_NODES) g_cnt[idx] = 0;
    int r = idx >> 4;          // row (EMB/4 = 16 float4 per row)
    int c = idx & 15;
    float4 v = (r < N_USER)
        ? reinterpret_cast<const float4*>(ue)[(size_t)r * 16 + c]
        : reinterpret_cast<const float4*>(ie)[(size_t)(r - N_USER) * 16 + c];
    reinterpret_cast<float4*>(g_ego)[idx] = v;
    *reinterpret_cast<float4*>(&g_all[(size_t)r * OUT_EMB + c * 4]) = v;
}

// ---------------------------------------------------------------------------
// ELL build: single pass, no scan. pos = atomicAdd(cnt[row]); write slot.
// ---------------------------------------------------------------------------
__global__ __launch_bounds__(256) void k_build(const int* __restrict__ arow,
                                               const int* __restrict__ acol,
                                               const float* __restrict__ aval) {
    int e = blockIdx.x * blockDim.x + threadIdx.x;
    if (e >= NNZ) return;
    int r = arow[e];
    int pos = atomicAdd(&g_cnt[r], 1);
    if (pos < ELL_CAP)
        g_ell[(size_t)r * ELL_CAP + pos] = make_int2(acol[e], __float_as_int(aval[e]));
}

// ---------------------------------------------------------------------------
// ELL SpMM: one warp per row; lane l accumulates dims [2l, 2l+1] in registers.
// ---------------------------------------------------------------------------
__global__ __launch_bounds__(256) void k_spmm_ell() {
    __shared__ int2 se[8][32];
    int gw = (blockIdx.x * 256 + threadIdx.x) >> 5;   // uniform within warp
    if (gw >= N_NODES) return;
    int lane = threadIdx.x & 31;
    int wl = threadIdx.x >> 5;
    int cnt = g_cnt[gw];
    if (cnt > ELL_CAP) cnt = ELL_CAP;
    const int2* row = &g_ell[(size_t)gw * ELL_CAP];
    float2 acc = make_float2(0.f, 0.f);
    for (int base = 0; base < cnt; base += 32) {
        int idx = base + lane;
        int2 ev = make_int2(0, 0);
        if (idx < cnt) ev = row[idx];
        se[wl][lane] = ev;
        __syncwarp();
        int n = cnt - base; if (n > 32) n = 32;
        #pragma unroll 4
        for (int j = 0; j < n; j++) {
            int2 e2 = se[wl][j];
            float val = __int_as_float(e2.y);
            float2 x = *reinterpret_cast<const float2*>(
                &g_ego[(size_t)e2.x * EMB + lane * 2]);
            acc.x = fmaf(val, x.x, acc.x);
            acc.y = fmaf(val, x.y, acc.y);
        }
        __syncwarp();
    }
    *reinterpret_cast<float2*>(&g_side[(size_t)gw * EMB + lane * 2]) = acc;
}

// ---------------------------------------------------------------------------
// Dense layer: ego_new = leaky( side@Wg + bg + (ego*side)@Wb + bb )
// 256 threads, 256 rows/block. Thread = 8 rows x 8 cols.
// Accumulators packed over ROW pairs (f32x2 = 2 rows), so s/p come straight
// out of LDS.128 with no packing; only W scalars get pack2'd (16/warp-i).
// Per warp-i: 4 W-LDS.128 (8wf) + 4 s/p-LDS.128 (4wf) + 16 pack + 64 ffma2.
// ---------------------------------------------------------------------------
__global__ __launch_bounds__(256, 2) void k_dense(const float* __restrict__ Wg,
                                                  const float* __restrict__ bg,
                                                  const float* __restrict__ Wb,
                                                  const float* __restrict__ bb,
                                                  int layer) {
    __shared__ float sWg[KT * EMB];        // 4KB
    __shared__ float sWb[KT * EMB];        // 4KB
    __shared__ float sS[KT * DROWS];       // 16KB  sS[i][row]
    __shared__ float sP[KT * DROWS];       // 16KB  sP[i][row]

    const int tid  = threadIdx.x;
    const int lane = tid & 31;
    const int wid  = tid >> 5;
    const int jt   = lane & 7;        // col-group 0..7 (8 cols each)
    const int slot = lane >> 3;       // 0..3 (8 rows each)
    const int lrow0 = wid * 32 + slot * 8;     // first of this thread's 8 rows
    const int row_base = blockIdx.x * DROWS;

    const float* Wgk = Wg + (size_t)layer * EMB * EMB;
    const float* Wbk = Wb + (size_t)layer * EMB * EMB;

    // acc[rp][c]: f32x2 = rows (lrow0+2rp, lrow0+2rp+1), col jt*8+c.
    unsigned long long acc[4][8];
    {   // bias seed from global (uniform per-jt addresses -> L1 broadcast)
        const float4* bg4 = reinterpret_cast<const float4*>(bg + layer * EMB);
        const float4* bb4 = reinterpret_cast<const float4*>(bb + layer * EMB);
        float4 b0 = bg4[jt * 2],     b1 = bg4[jt * 2 + 1];
        float4 c0 = bb4[jt * 2],     c1 = bb4[jt * 2 + 1];
        float bsum[8] = {b0.x + c0.x, b0.y + c0.y, b0.z + c0.z, b0.w + c0.w,
                         b1.x + c1.x, b1.y + c1.y, b1.z + c1.z, b1.w + c1.w};
        #pragma unroll
        for (int c = 0; c < 8; c++) {
            unsigned long long bp = pack2(bsum[c]);
            #pragma unroll
            for (int rp = 0; rp < 4; rp++) acc[rp][c] = bp;
        }
    }

    // staging role: this thread stages global row (row_base + tid), clamped
    const int crow = min(row_base + tid, N_NODES - 1);

    for (int kt = 0; kt < EMB / KT; kt++) {
        // --- stage W tile [KT][64]: one float4 per thread per matrix ---
        {
            int i_l = tid >> 4, c4 = tid & 15;
            size_t g = (size_t)(kt * KT + i_l) * EMB + c4 * 4;
            float4 wgv = *reinterpret_cast<const float4*>(&Wgk[g]);
            float4 wbv = *reinterpret_cast<const float4*>(&Wbk[g]);
            *reinterpret_cast<float4*>(&sWg[i_l * EMB + c4 * 4]) = wgv;
            *reinterpret_cast<float4*>(&sWb[i_l * EMB + c4 * 4]) = wbv;
        }
        // --- stage s/p transposed: row = tid, dims kt*KT..+KT ---
        #pragma unroll
        for (int q = 0; q < KT / 4; q++) {
            size_t g = (size_t)crow * EMB + kt * KT + q * 4;
            float4 sv = *reinterpret_cast<const float4*>(&g_side[g]);
            float4 ev = *reinterpret_cast<const float4*>(&g_ego[g]);
            sS[(q * 4 + 0) * DROWS + tid] = sv.x;
            sS[(q * 4 + 1) * DROWS + tid] = sv.y;
            sS[(q * 4 + 2) * DROWS + tid] = sv.z;
            sS[(q * 4 + 3) * DROWS + tid] = sv.w;
            sP[(q * 4 + 0) * DROWS + tid] = sv.x * ev.x;
            sP[(q * 4 + 1) * DROWS + tid] = sv.y * ev.y;
            sP[(q * 4 + 2) * DROWS + tid] = sv.z * ev.z;
            sP[(q * 4 + 3) * DROWS + tid] = sv.w * ev.w;
        }
        __syncthreads();

        #pragma unroll
        for (int i = 0; i < KT; i++) {
            // s/p row pairs straight from LDS.128 (no packing)
            ulonglong2 sA = *reinterpret_cast<const ulonglong2*>(&sS[i * DROWS + lrow0]);
            ulonglong2 sB2 = *reinterpret_cast<const ulonglong2*>(&sS[i * DROWS + lrow0 + 4]);
            ulonglong2 pA = *reinterpret_cast<const ulonglong2*>(&sP[i * DROWS + lrow0]);
            ulonglong2 pB2 = *reinterpret_cast<const ulonglong2*>(&sP[i * DROWS + lrow0 + 4]);
            unsigned long long s2[4] = {sA.x, sA.y, sB2.x, sB2.y};
            unsigned long long p2[4] = {pA.x, pA.y, pB2.x, pB2.y};

            // W scalars for this thread's 8 cols
            float4 wg0 = *reinterpret_cast<const float4*>(&sWg[i * EMB + jt * 8]);
            float4 wg1 = *reinterpret_cast<const float4*>(&sWg[i * EMB + jt * 8 + 4]);
            float4 wb0 = *reinterpret_cast<const float4*>(&sWb[i * EMB + jt * 8]);
            float4 wb1 = *reinterpret_cast<const float4*>(&sWb[i * EMB + jt * 8 + 4]);
            float wgf[8] = {wg0.x, wg0.y, wg0.z, wg0.w, wg1.x, wg1.y, wg1.z, wg1.w};
            float wbf[8] = {wb0.x, wb0.y, wb0.z, wb0.w, wb1.x, wb1.y, wb1.z, wb1.w};

            #pragma unroll
            for (int c = 0; c < 8; c++) {
                unsigned long long wgp = pack2(wgf[c]);
                unsigned long long wbp = pack2(wbf[c]);
                #pragma unroll
                for (int rp = 0; rp < 4; rp++) {
                    acc[rp][c] = ffma2(s2[rp], wgp, acc[rp][c]);
                    acc[rp][c] = ffma2(p2[rp], wbp, acc[rp][c]);
                }
            }
        }
        __syncthreads();
    }

    // --- epilogue: leaky + row-norm (8-lane shfl) + stores, 2 rows per rp ---
    #pragma unroll
    for (int rp = 0; rp < 4; rp++) {
        float a0[8], a1[8];            // row lrow0+2rp, row lrow0+2rp+1
        #pragma unroll
        for (int c = 0; c < 8; c++) {
            float2 u = unpack2(acc[rp][c]);
            a0[c] = u.x;
            a1[c] = u.y;
        }
        float n0 = 0.f, n1 = 0.f;
        #pragma unroll
        for (int c = 0; c < 8; c++) {
            float v0 = a0[c]; v0 = (v0 > 0.f) ? v0 : 0.2f * v0; a0[c] = v0; n0 += v0 * v0;
            float v1 = a1[c]; v1 = (v1 > 0.f) ? v1 : 0.2f * v1; a1[c] = v1; n1 += v1 * v1;
        }
        #pragma unroll
        for (int m = 1; m < 8; m <<= 1) {
            n0 += __shfl_xor_sync(0xffffffffu, n0, m, 8);
            n1 += __shfl_xor_sync(0xffffffffu, n1, m, 8);
        }
        float inv0 = 1.0f / fmaxf(sqrtf(n0), 1e-12f);
        float inv1 = 1.0f / fmaxf(sqrtf(n1), 1e-12f);

        int grow0 = row_base + lrow0 + rp * 2;
        if (grow0 < N_NODES) {
            float* egp = &g_ego[(size_t)grow0 * EMB + jt * 8];
            reinterpret_cast<float4*>(egp)[0] = make_float4(a0[0], a0[1], a0[2], a0[3]);
            reinterpret_cast<float4*>(egp)[1] = make_float4(a0[4], a0[5], a0[6], a0[7]);
            float* alp = &g_all[(size_t)grow0 * OUT_EMB + (layer + 1) * EMB + jt * 8];
            reinterpret_cast<float4*>(alp)[0] =
                make_float4(a0[0] * inv0, a0[1] * inv0, a0[2] * inv0, a0[3] * inv0);
            reinterpret_cast<float4*>(alp)[1] =
                make_float4(a0[4] * inv0, a0[5] * inv0, a0[6] * inv0, a0[7] * inv0);
        }
        int grow1 = grow0 + 1;
        if (grow1 < N_NODES) {
            float* egp = &g_ego[(size_t)grow1 * EMB + jt * 8];
            reinterpret_cast<float4*>(egp)[0] = make_float4(a1[0], a1[1], a1[2], a1[3]);
            reinterpret_cast<float4*>(egp)[1] = make_float4(a1[4], a1[5], a1[6], a1[7]);
            float* alp = &g_all[(size_t)grow1 * OUT_EMB + (layer + 1) * EMB + jt * 8];
            reinterpret_cast<float4*>(alp)[0] =
                make_float4(a1[0] * inv1, a1[1] * inv1, a1[2] * inv1, a1[3] * inv1);
            reinterpret_cast<float4*>(alp)[1] =
                make_float4(a1[4] * inv1, a1[5] * inv1, a1[6] * inv1, a1[7] * inv1);
        }
    }
}

// ---------------------------------------------------------------------------
// Final gather: out = [ all[users], all[N_USER+pos], all[N_USER+neg] ]
// ---------------------------------------------------------------------------
__global__ __launch_bounds__(256) void k_gather(const int* __restrict__ users,
                                                const int* __restrict__ pos,
                                                const int* __restrict__ neg,
                                                float* __restrict__ out) {
    int t = blockIdx.x * blockDim.x + threadIdx.x;
    const int total = 3 * BATCH * (OUT_EMB / 4);
    if (t >= total) return;
    int g = t / (BATCH * (OUT_EMB / 4));
    int rem = t - g * (BATCH * (OUT_EMB / 4));
    int b = rem >> 6;          // OUT_EMB/4 = 64 float4 per row
    int f = rem & 63;
    int src;
    if (g == 0)      src = users[b];
    else if (g == 1) src = N_USER + pos[b];
    else             src = N_USER + neg[b];
    reinterpret_cast<float4*>(out)[t] =
        reinterpret_cast<const float4*>(&g_all[(size_t)src * OUT_EMB])[f];
}

// ---------------------------------------------------------------------------
extern "C" void kernel_launch(void* const* d_in, const int* in_sizes, int n_in,
                              void* d_out, int out_size) {
    const int*   users = (const int*)   d_in[0];
    const int*   pos   = (const int*)   d_in[1];
    const int*   neg   = (const int*)   d_in[2];
    const int*   arow  = (const int*)   d_in[3];
    const int*   acol  = (const int*)   d_in[4];
    const float* aval  = (const float*) d_in[5];
    const float* ue    = (const float*) d_in[6];
    const float* ie    = (const float*) d_in[7];
    const float* Wg    = (const float*) d_in[8];
    const float* bg    = (const float*) d_in[9];
    const float* Wb    = (const float*) d_in[10];
    const float* bb    = (const float*) d_in[11];
    float* out = (float*)d_out;

    k_init<<<(N_NODES * EMB / 4 + 255) / 256, 256>>>(ue, ie);

    // One-pass ELL build (no histogram, no scan) — amortized over 3 layers
    k_build<<<(NNZ + 255) / 256, 256>>>(arow, acol, aval);

    const int dense_grid = (N_NODES + DROWS - 1) / DROWS;
    for (int k = 0; k < N_LAYERS; k++) {
        k_spmm_ell<<<(N_NODES * 32 + 255) / 256, 256>>>();
        k_dense<<<dense_grid, 256>>>(Wg, bg, Wb, bb, k);
    }

    k_gather<<<(3 * BATCH * (OUT_EMB / 4) + 255) / 256, 256>>>(users, pos, neg, out);
}